// round 16
// baseline (speedup 1.0000x reference)
#include <cuda_runtime.h>
#include <cuda_fp16.h>
#include <mma.h>
#include <math.h>

using namespace nvcuda;

#define NN 10000
#define EE 320000
#define BB 8
#define SS 12
#define HH 64
#define HEADS 4
#define CC 16
#define LL 3
#define PP 3
#define BN (BB * NN)
#define EPSF 1e-5f

__device__ __align__(16) float d_h[BN * HH];
__device__ __align__(16) __half d_h16[BN * HH];
__device__ __align__(16) __half d_q16[BN * HH];   // batch-major [b*NN+n][64]
__device__ __align__(16) __half d_s16[BN * HH];   // batch-major
// node-major: [n][b][64]
__device__ __align__(16) __half d_k16[BN * HH];
__device__ __align__(16) __half d_v16[BN * HH];
__device__ __align__(16) __half d_W16all[LL * 4 * HH * HH];
__device__ int d_src[EE];
__device__ int d_dst[EE];
__device__ int d_deg[NN];
__device__ int d_ptr[NN + 1];
__device__ int d_cnt[NN];
__device__ int d_csr_src[EE];
__device__ int d_is64;
__device__ int d_bsum[40];
__device__ int d_boff[40];

// thread 0 detects edge dtype; all threads zero the degree array
__global__ void detect_zero_kernel(const void* ei) {
    int tid = threadIdx.x;
    if (tid == 0) {
        const long long* p = (const long long*)ei;
        int is64 = 1;
        for (int i = 0; i < 64; i++) {
            long long v = p[i];
            if (v < 0 || v >= NN) { is64 = 0; break; }
        }
        d_is64 = is64;
    }
    for (int idx = tid; idx < NN; idx += 1024) d_deg[idx] = 0;
}

__global__ void convert_kernel(const void* ei) {
    int e = blockIdx.x * blockDim.x + threadIdx.x;
    if (e >= EE) return;
    int s, d;
    if (d_is64) {
        const long long* p = (const long long*)ei;
        s = (int)p[e];
        d = (int)p[EE + e];
    } else {
        const int* p = (const int*)ei;
        s = p[e];
        d = p[EE + e];
    }
    d_src[e] = s;
    d_dst[e] = d;
    atomicAdd(&d_deg[d], 1);
}

// multi-block scan, phase 1: per-block sums (40 blocks x 256)
__global__ void scan1_kernel() {
    __shared__ int wsum[8];
    int idx = blockIdx.x * 256 + threadIdx.x;
    int v = (idx < NN) ? d_deg[idx] : 0;
    int lane = threadIdx.x & 31, wid = threadIdx.x >> 5;
    int t = v;
#pragma unroll
    for (int o = 1; o < 32; o <<= 1) t += __shfl_xor_sync(0xFFFFFFFF, t, o);
    if (lane == 0) wsum[wid] = t;
    __syncthreads();
    if (threadIdx.x == 0) {
        int a = 0;
#pragma unroll
        for (int i = 0; i < 8; i++) a += wsum[i];
        d_bsum[blockIdx.x] = a;
    }
}

// phase 2: exclusive scan of the 40 block sums (1 block, 64 threads)
__global__ void scan2_kernel() {
    __shared__ int vals[64];
    int tid = threadIdx.x;
    vals[tid] = (tid < 40) ? d_bsum[tid] : 0;
    __syncthreads();
    if (tid == 0) {
        int a = 0;
        for (int i = 0; i < 40; i++) { int t = vals[i]; vals[i] = a; a += t; }
    }
    __syncthreads();
    if (tid < 40) d_boff[tid] = vals[tid];
}

// phase 3: block-local exclusive scan + offset -> d_ptr, d_cnt
__global__ void scan3_kernel() {
    __shared__ int wsum[8];
    int idx = blockIdx.x * 256 + threadIdx.x;
    int v = (idx < NN) ? d_deg[idx] : 0;
    int lane = threadIdx.x & 31, wid = threadIdx.x >> 5;
    int incl = v;
#pragma unroll
    for (int o = 1; o < 32; o <<= 1) {
        int t = __shfl_up_sync(0xFFFFFFFF, incl, o);
        if (lane >= o) incl += t;
    }
    if (lane == 31) wsum[wid] = incl;
    __syncthreads();
    if (wid == 0 && lane < 8) {
        int t = wsum[lane];
        int a = t;
#pragma unroll
        for (int o = 1; o < 8; o <<= 1) {
            int u = __shfl_up_sync(0xFF, a, o);
            if (lane >= o) a += u;
        }
        wsum[lane] = a - t;   // exclusive warp offsets
    }
    __syncthreads();
    int excl = incl - v + wsum[wid] + d_boff[blockIdx.x];
    if (idx < NN) {
        d_ptr[idx] = excl;
        d_cnt[idx] = excl;
    }
    if (idx == NN - 1) d_ptr[NN] = EE;
}

__global__ void scatter_kernel() {
    int e = blockIdx.x * blockDim.x + threadIdx.x;
    if (e >= EE) return;
    int d = d_dst[e];
    int pos = atomicAdd(&d_cnt[d], 1);
    d_csr_src[pos] = d_src[e];
}

__global__ void convw_kernel(const float* __restrict__ Wq, const float* __restrict__ Wk,
                             const float* __restrict__ Wv, const float* __restrict__ Wsk) {
    int idx = blockIdx.x * blockDim.x + threadIdx.x;
    if (idx >= LL * 4 * 4096) return;
    int l = idx >> 14;
    int sel = (idx >> 12) & 3;
    int j = idx & 4095;
    const float* W = (sel == 0) ? Wq : (sel == 1) ? Wk : (sel == 2) ? Wv : Wsk;
    d_W16all[idx] = __float2half(W[l * 4096 + j]);
}

__global__ void input_proj_kernel(const float* __restrict__ x,
                                  const float* __restrict__ inW,
                                  const float* __restrict__ inb) {
    __shared__ float xs[SS * 64];
    __shared__ float Ws[SS * HH];
    int b = blockIdx.y;
    int nb = blockIdx.x * 64;
    int tid = threadIdx.x;
    for (int idx = tid; idx < SS * HH; idx += 256) Ws[idx] = inW[idx];
    for (int idx = tid; idx < SS * 64; idx += 256) {
        int s = idx >> 6, i = idx & 63;
        int n = nb + i;
        xs[idx] = (n < NN) ? x[(size_t)b * SS * NN + s * NN + n] : 0.0f;
    }
    __syncthreads();
    int j = tid & 63;
    int i0 = (tid >> 6) * 16;
    float bj = inb[j];
    for (int ii = 0; ii < 16; ii++) {
        int i = i0 + ii;
        int n = nb + i;
        if (n >= NN) break;
        float acc = bj;
#pragma unroll
        for (int s = 0; s < SS; s++) acc += xs[s * 64 + i] * Ws[s * HH + j];
        size_t o = ((size_t)b * NN + n) * HH + j;
        d_h[o] = acc;
        d_h16[o] = __float2half(acc);
    }
}

// 512 threads = 16 warps: warp = rowtile(0-3) + 4*sel(0-3). 64 rows per block.
// All outputs fp16: q/s batch-major, k/v node-major.
__global__ void gemm_wmma_kernel(int layer,
                                 const float* __restrict__ b0, const float* __restrict__ b1,
                                 const float* __restrict__ b2, const float* __restrict__ b3) {
    __shared__ __half As[64 * 72];
    __shared__ float stage[16][256];
    int tid = threadIdx.x;
    int warp = tid >> 5;
    int lane = tid & 31;
    int rt = warp & 3;
    int wsel = warp >> 2;
    int base0 = blockIdx.x * 64;
    int base = base0 + rt * 16;

    {
        int row = tid >> 3, col = (tid & 7) * 8;
        uint4 vsrc = *(const uint4*)(d_h16 + (size_t)(base0 + row) * 64 + col);
        *(uint4*)(As + row * 72 + col) = vsrc;
    }
    __syncthreads();

    const __half* B = d_W16all + ((size_t)layer * 4 + wsel) * 4096;

    wmma::fragment<wmma::accumulator, 16, 16, 16, float> acc[4];
#pragma unroll
    for (int nt = 0; nt < 4; nt++) wmma::fill_fragment(acc[nt], 0.0f);

#pragma unroll
    for (int kk = 0; kk < 4; kk++) {
        wmma::fragment<wmma::matrix_a, 16, 16, 16, __half, wmma::row_major> a;
        wmma::load_matrix_sync(a, As + (rt * 16) * 72 + kk * 16, 72);
#pragma unroll
        for (int nt = 0; nt < 4; nt++) {
            wmma::fragment<wmma::matrix_b, 16, 16, 16, __half, wmma::row_major> b;
            wmma::load_matrix_sync(b, B + (size_t)kk * 16 * 64 + nt * 16, 64);
            wmma::mma_sync(acc[nt], a, b, acc[nt]);
        }
    }

    const float* bias = (wsel == 0) ? b0 : (wsel == 1) ? b1 : (wsel == 2) ? b2 : b3;
    float* stg = &stage[warp][0];
    int r = lane >> 1, c0 = (lane & 1) * 8;
    int gr = base + r;
    int gb = gr / NN;
    int gn = gr - gb * NN;
    __half* outp = (wsel == 0) ? d_q16 : (wsel == 1) ? d_k16 : (wsel == 2) ? d_v16 : d_s16;
    size_t rowoff = (wsel == 0 || wsel == 3) ? (size_t)gr * 64
                                             : ((size_t)gn * BB + gb) * 64;
#pragma unroll
    for (int nt = 0; nt < 4; nt++) {
        wmma::store_matrix_sync(stg, acc[nt], 16, wmma::mem_row_major);
        __syncwarp();
        int gc = nt * 16 + c0;
        float vals[8];
#pragma unroll
        for (int t = 0; t < 8; t++) vals[t] = stg[r * 16 + c0 + t] + bias[gc + t];
        __half2 h2[4];
#pragma unroll
        for (int t = 0; t < 4; t++) h2[t] = __floats2half2_rn(vals[2 * t], vals[2 * t + 1]);
        *(uint4*)(outp + rowoff + gc) = *(uint4*)h2;
        __syncwarp();
    }
}

// TWO warps per NODE (edge list split by pair parity) to double outstanding
// loads per node. lane = b*4 + head; in-lane dot; smem combine; warp A does
// the epilogue. 256 threads = 8 warps = 4 nodes/block.
__global__ void __launch_bounds__(256) edge_node_kernel(const float* __restrict__ g,
                                                        const float* __restrict__ bta) {
    __shared__ float partial[4][32][17];
    int warp = threadIdx.x >> 5;
    int wpair = warp >> 1;    // node slot in block (0-3)
    int wsub = warp & 1;      // which half of the edge list
    int lane = threadIdx.x & 31;
    int n = blockIdx.x * 4 + wpair;
    int b = lane >> 2;
    int head = lane & 3;
    int rowbase = (b * NN + n) * HH + head * CC;   // batch-major
    int kvoff = b * HH + head * CC;                // within node block (halves)

    float q[16];
    {
        uint4 qa = *(const uint4*)(d_q16 + rowbase);
        uint4 qb = *(const uint4*)(d_q16 + rowbase + 8);
        const __half2* qh = (const __half2*)&qa;
#pragma unroll
        for (int t = 0; t < 4; t++) {
            float2 f = __half22float2(qh[t]);
            q[2 * t] = f.x; q[2 * t + 1] = f.y;
        }
        qh = (const __half2*)&qb;
#pragma unroll
        for (int t = 0; t < 4; t++) {
            float2 f = __half22float2(qh[t]);
            q[8 + 2 * t] = f.x; q[8 + 2 * t + 1] = f.y;
        }
    }

    int start = d_ptr[n];
    int end = d_ptr[n + 1];
    int mystart = start + 2 * wsub;

    float ac[16];
#pragma unroll
    for (int t = 0; t < 16; t++) ac[t] = 0.f;
    float den = 0.f;

    if (mystart < end) {
        int s0n = d_csr_src[mystart];
        int s1n = d_csr_src[(mystart + 1 < end) ? (mystart + 1) : mystart];
        for (int i = mystart; i < end; i += 4) {
            int s0 = s0n, s1 = s1n;
            bool va1 = (i + 1 < end);
            int nj0 = (i + 4 < end) ? (i + 4) : i;
            int nj1 = (i + 5 < end) ? (i + 5) : i;
            s0n = d_csr_src[nj0];
            s1n = d_csr_src[nj1];
            size_t a0 = (size_t)s0 * 512 + kvoff;
            size_t a1 = (size_t)s1 * 512 + kvoff;
            uint4 k0a = *(const uint4*)(d_k16 + a0);
            uint4 k0b = *(const uint4*)(d_k16 + a0 + 8);
            uint4 v0a = *(const uint4*)(d_v16 + a0);
            uint4 v0b = *(const uint4*)(d_v16 + a0 + 8);
            uint4 k1a = *(const uint4*)(d_k16 + a1);
            uint4 k1b = *(const uint4*)(d_k16 + a1 + 8);
            uint4 v1a = *(const uint4*)(d_v16 + a1);
            uint4 v1b = *(const uint4*)(d_v16 + a1 + 8);

            {
                const __half2* kh = (const __half2*)&k0a;
                float p = 0.f;
#pragma unroll
                for (int t = 0; t < 4; t++) {
                    float2 f = __half22float2(kh[t]);
                    p += q[2 * t] * f.x + q[2 * t + 1] * f.y;
                }
                kh = (const __half2*)&k0b;
#pragma unroll
                for (int t = 0; t < 4; t++) {
                    float2 f = __half22float2(kh[t]);
                    p += q[8 + 2 * t] * f.x + q[8 + 2 * t + 1] * f.y;
                }
                float wt = __expf(p * 0.25f);
                den += wt;
                const __half2* vh = (const __half2*)&v0a;
#pragma unroll
                for (int t = 0; t < 4; t++) {
                    float2 f = __half22float2(vh[t]);
                    ac[2 * t] += wt * f.x; ac[2 * t + 1] += wt * f.y;
                }
                vh = (const __half2*)&v0b;
#pragma unroll
                for (int t = 0; t < 4; t++) {
                    float2 f = __half22float2(vh[t]);
                    ac[8 + 2 * t] += wt * f.x; ac[8 + 2 * t + 1] += wt * f.y;
                }
            }
            {
                const __half2* kh = (const __half2*)&k1a;
                float p = 0.f;
#pragma unroll
                for (int t = 0; t < 4; t++) {
                    float2 f = __half22float2(kh[t]);
                    p += q[2 * t] * f.x + q[2 * t + 1] * f.y;
                }
                kh = (const __half2*)&k1b;
#pragma unroll
                for (int t = 0; t < 4; t++) {
                    float2 f = __half22float2(kh[t]);
                    p += q[8 + 2 * t] * f.x + q[8 + 2 * t + 1] * f.y;
                }
                float wt = va1 ? __expf(p * 0.25f) : 0.f;
                den += wt;
                const __half2* vh = (const __half2*)&v1a;
#pragma unroll
                for (int t = 0; t < 4; t++) {
                    float2 f = __half22float2(vh[t]);
                    ac[2 * t] += wt * f.x; ac[2 * t + 1] += wt * f.y;
                }
                vh = (const __half2*)&v1b;
#pragma unroll
                for (int t = 0; t < 4; t++) {
                    float2 f = __half22float2(vh[t]);
                    ac[8 + 2 * t] += wt * f.x; ac[8 + 2 * t + 1] += wt * f.y;
                }
            }
        }
    }

    // combine the two warps' partials via smem
    if (wsub == 1) {
#pragma unroll
        for (int t = 0; t < 16; t++) partial[wpair][lane][t] = ac[t];
        partial[wpair][lane][16] = den;
    }
    __syncthreads();
    if (wsub == 1) return;
#pragma unroll
    for (int t = 0; t < 16; t++) ac[t] += partial[wpair][lane][t];
    den += partial[wpair][lane][16];

    float inv = (den > 0.f) ? (1.0f / den) : 0.f;
    float hv[16], sv[16];
    {
        const float4* hp = (const float4*)(d_h + rowbase);
#pragma unroll
        for (int t = 0; t < 4; t++) {
            float4 f = hp[t];
            hv[4 * t] = f.x; hv[4 * t + 1] = f.y; hv[4 * t + 2] = f.z; hv[4 * t + 3] = f.w;
        }
        uint4 sa = *(const uint4*)(d_s16 + rowbase);
        uint4 sb = *(const uint4*)(d_s16 + rowbase + 8);
        const __half2* sh = (const __half2*)&sa;
#pragma unroll
        for (int t = 0; t < 4; t++) {
            float2 f = __half22float2(sh[t]);
            sv[2 * t] = f.x; sv[2 * t + 1] = f.y;
        }
        sh = (const __half2*)&sb;
#pragma unroll
        for (int t = 0; t < 4; t++) {
            float2 f = __half22float2(sh[t]);
            sv[8 + 2 * t] = f.x; sv[8 + 2 * t + 1] = f.y;
        }
    }

    float tv[16];
    float sum = 0.f, sq = 0.f;
#pragma unroll
    for (int t = 0; t < 16; t++) {
        tv[t] = hv[t] + ac[t] * inv + sv[t];
        sum += tv[t];
        sq += tv[t] * tv[t];
    }
    sum += __shfl_xor_sync(0xFFFFFFFF, sum, 1);
    sq  += __shfl_xor_sync(0xFFFFFFFF, sq, 1);
    sum += __shfl_xor_sync(0xFFFFFFFF, sum, 2);
    sq  += __shfl_xor_sync(0xFFFFFFFF, sq, 2);

    float mean = sum * (1.0f / 64.0f);
    float var = sq * (1.0f / 64.0f) - mean * mean;
    float rs = rsqrtf(var + EPSF);

    float ov[16];
#pragma unroll
    for (int t = 0; t < 4; t++) {
        float4 gv = *(const float4*)(g + head * CC + 4 * t);
        float4 ev = *(const float4*)(bta + head * CC + 4 * t);
        ov[4 * t]     = (tv[4 * t]     - mean) * rs * gv.x + ev.x;
        ov[4 * t + 1] = (tv[4 * t + 1] - mean) * rs * gv.y + ev.y;
        ov[4 * t + 2] = (tv[4 * t + 2] - mean) * rs * gv.z + ev.z;
        ov[4 * t + 3] = (tv[4 * t + 3] - mean) * rs * gv.w + ev.w;
    }

    float4* hp = (float4*)(d_h + rowbase);
#pragma unroll
    for (int t = 0; t < 4; t++)
        hp[t] = make_float4(ov[4 * t], ov[4 * t + 1], ov[4 * t + 2], ov[4 * t + 3]);
    __half2 hh[8];
#pragma unroll
    for (int t = 0; t < 8; t++) hh[t] = __floats2half2_rn(ov[2 * t], ov[2 * t + 1]);
    *(uint4*)(d_h16 + rowbase)     = *(uint4*)&hh[0];
    *(uint4*)(d_h16 + rowbase + 8) = *(uint4*)&hh[4];
}

__global__ void out_proj_kernel(const float* __restrict__ oW,
                                const float* __restrict__ ob,
                                float* __restrict__ out) {
    int t = blockIdx.x * blockDim.x + threadIdx.x;
    if (t >= BN) return;
    int b = t / NN, n = t % NN;
    const float4* hr = (const float4*)(d_h + (size_t)t * 64);
    float a0 = ob[0], a1 = ob[1], a2 = ob[2];
#pragma unroll
    for (int i = 0; i < 16; i++) {
        float4 hv = hr[i];
        int h0 = i * 4;
        a0 += hv.x * oW[(h0 + 0) * PP + 0]; a1 += hv.x * oW[(h0 + 0) * PP + 1]; a2 += hv.x * oW[(h0 + 0) * PP + 2];
        a0 += hv.y * oW[(h0 + 1) * PP + 0]; a1 += hv.y * oW[(h0 + 1) * PP + 1]; a2 += hv.y * oW[(h0 + 1) * PP + 2];
        a0 += hv.z * oW[(h0 + 2) * PP + 0]; a1 += hv.z * oW[(h0 + 2) * PP + 1]; a2 += hv.z * oW[(h0 + 2) * PP + 2];
        a0 += hv.w * oW[(h0 + 3) * PP + 0]; a1 += hv.w * oW[(h0 + 3) * PP + 1]; a2 += hv.w * oW[(h0 + 3) * PP + 2];
    }
    out[(size_t)b * PP * NN + 0 * NN + n] = a0;
    out[(size_t)b * PP * NN + 1 * NN + n] = a1;
    out[(size_t)b * PP * NN + 2 * NN + n] = a2;
}

extern "C" void kernel_launch(void* const* d_in, const int* in_sizes, int n_in,
                              void* d_out, int out_size) {
    const float* x    = (const float*)d_in[0];
    const void*  ei   = d_in[1];
    const float* inW  = (const float*)d_in[2];
    const float* inb  = (const float*)d_in[3];
    const float* Wq   = (const float*)d_in[4];
    const float* bq   = (const float*)d_in[5];
    const float* Wk   = (const float*)d_in[6];
    const float* bk   = (const float*)d_in[7];
    const float* Wv   = (const float*)d_in[8];
    const float* bv   = (const float*)d_in[9];
    const float* Wsk  = (const float*)d_in[10];
    const float* bsk  = (const float*)d_in[11];
    const float* lng  = (const float*)d_in[12];
    const float* lnb  = (const float*)d_in[13];
    const float* oW   = (const float*)d_in[14];
    const float* ob   = (const float*)d_in[15];
    float* out = (float*)d_out;

    detect_zero_kernel<<<1, 1024>>>(ei);
    convert_kernel<<<EE / 256, 256>>>(ei);
    scan1_kernel<<<40, 256>>>();
    scan2_kernel<<<1, 64>>>();
    scan3_kernel<<<40, 256>>>();
    scatter_kernel<<<EE / 256, 256>>>();
    convw_kernel<<<(LL * 4 * 4096 + 255) / 256, 256>>>(Wq, Wk, Wv, Wsk);

    dim3 ipg((NN + 63) / 64, BB);
    input_proj_kernel<<<ipg, 256>>>(x, inW, inb);

    for (int l = 0; l < LL; l++) {
        gemm_wmma_kernel<<<BN / 64, 512>>>(l, bq + l * HH, bk + l * HH,
                                           bv + l * HH, bsk + l * HH);
        edge_node_kernel<<<NN / 4, 256>>>(lng, lnb);
    }

    out_proj_kernel<<<(BN + 255) / 256, 256>>>(oW, ob, out);
}